// round 3
// baseline (speedup 1.0000x reference)
#include <cuda_runtime.h>
#include <cuda_bf16.h>
#include <stdint.h>

// ============================================================================
// VQ argmin via mma.sync (sm_80 baseline PTX -> HMMA on Blackwell tensor pipe).
//   cvt:    codebook -> bf16 copy;  csq = ||c||^2 (fp32 exact)
//   sweep:  per CTA 128 tokens; loop 64-code tiles; bf16 MMA approx distances;
//           per tile: update running min -> sync -> collect cands within MARGIN
//   rescore: exact fp32 distance over candidates (full scan if overflow)
//   gather: out = codebook[idx]
// ============================================================================

#define NTOK   16384
#define DIM    256
#define KCODES 4096
#define HW     1024
#define MTILE  128
#define NTILE  64
#define ITERS  (KCODES / NTILE)
#define CAP    128
#define MARGIN 16.0f
#define RS     528          // smem row stride bytes (256 bf16 + 8 pad)

// SMEM layout (dynamic)
#define SM_CSQ  0                     // 4096 f32 = 16384
#define SM_MIN  16384                 // 128 u32
#define SM_CNT  16896                 // 128 i32
#define SM_A    17408                 // 128 * 528 = 67584
#define SM_B    84992                 // 2 * 64 * 528 = 67584
#define SM_TOT  152576

__device__ float          g_csq[KCODES];
__device__ __nv_bfloat16  g_cb16[KCODES * DIM];
__device__ int            g_cnt[NTOK];
__device__ int            g_cand[(size_t)NTOK * CAP];
__device__ int            g_idx[NTOK];

// ---------------- helpers ----------------
__device__ __forceinline__ uint32_t smem_u32(const void* p) {
    uint32_t a;
    asm("{ .reg .u64 t; cvta.to.shared.u64 t, %1; cvt.u32.u64 %0, t; }" : "=r"(a) : "l"(p));
    return a;
}
__device__ __forceinline__ unsigned ford(float f) {        // order-preserving
    unsigned u = __float_as_uint(f);
    return (u & 0x80000000u) ? ~u : (u | 0x80000000u);
}
__device__ __forceinline__ float funord(unsigned u) {
    u = (u & 0x80000000u) ? (u & 0x7FFFFFFFu) ^ 0x80000000u ^ 0x80000000u : ~u;
    // decode: if top bit set -> original nonneg: bits = u ^ 0x80000000
    return 0.f; // unused (see below)
}
__device__ __forceinline__ float ford_inv(unsigned u) {
    unsigned b = (u & 0x80000000u) ? (u ^ 0x80000000u) : ~u;
    return __uint_as_float(b);
}

#define LDSM4(r, a) asm volatile( \
    "ldmatrix.sync.aligned.m8n8.x4.shared.b16 {%0,%1,%2,%3}, [%4];" \
    : "=r"((r)[0]), "=r"((r)[1]), "=r"((r)[2]), "=r"((r)[3]) : "r"(a))

#define MMA16816(c, A, B0, B1) asm volatile( \
    "mma.sync.aligned.m16n8k16.row.col.f32.bf16.bf16.f32 " \
    "{%0,%1,%2,%3},{%4,%5,%6,%7},{%8,%9},{%0,%1,%2,%3};" \
    : "+f"((c)[0]), "+f"((c)[1]), "+f"((c)[2]), "+f"((c)[3]) \
    : "r"((A)[0]), "r"((A)[1]), "r"((A)[2]), "r"((A)[3]), "r"(B0), "r"(B1))

#define CP16(d, s)  asm volatile("cp.async.cg.shared.global [%0], [%1], 16;" :: "r"(d), "l"(s))
#define CPCOMMIT()  asm volatile("cp.async.commit_group;" ::: "memory")
#define CPWAIT1()   asm volatile("cp.async.wait_group 1;" ::: "memory")
#define CPWAIT0()   asm volatile("cp.async.wait_group 0;" ::: "memory")

// ---------------- small kernels ----------------
__global__ void cvt_kernel(const float* __restrict__ cb) {
    int i = blockIdx.x * blockDim.x + threadIdx.x;
    if (i < KCODES * DIM) g_cb16[i] = __float2bfloat16_rn(cb[i]);
}
__global__ void csq_kernel(const float* __restrict__ cb) {
    int k = blockIdx.x * blockDim.x + threadIdx.x;
    if (k >= KCODES) return;
    const float4* row = reinterpret_cast<const float4*>(cb + (size_t)k * DIM);
    float s = 0.f;
#pragma unroll
    for (int i = 0; i < DIM / 4; i++) {
        float4 v = row[i];
        s += v.x * v.x + v.y * v.y + v.z * v.z + v.w * v.w;
    }
    g_csq[k] = s;
}

// ---------------- main sweep ----------------
__global__ __launch_bounds__(256, 1) void sweep_kernel(const float* __restrict__ x) {
    extern __shared__ char sm[];
    float*    csq_s = reinterpret_cast<float*>(sm + SM_CSQ);
    unsigned* minu  = reinterpret_cast<unsigned*>(sm + SM_MIN);
    int*      cnts  = reinterpret_cast<int*>(sm + SM_CNT);
    const uint32_t sb = smem_u32(sm);

    const int tid  = threadIdx.x;
    const int lane = tid & 31;
    const int w    = tid >> 5;
    const int wm   = w & 3;        // M warp (32 tokens)
    const int wn   = w >> 2;       // N warp (32 codes)
    const int n0   = blockIdx.x * MTILE;

    // ---- loads / init ----
    for (int i = tid; i < KCODES; i += 256) csq_s[i] = g_csq[i];
    if (tid < MTILE) { minu[tid] = 0xFFFFFFFFu; cnts[tid] = 0; }

    // A tile: x[token][dim] bf16 into smem (token row-major, RS stride)
    {
        const float* xb = x + (size_t)(n0 >> 10) * DIM * HW + (n0 & (HW - 1));
        for (int p = tid; p < MTILE * (DIM / 2); p += 256) {
            int tok = p & (MTILE - 1);
            int dp  = p >> 7;                       // dim pair
            float v0 = xb[(size_t)(2 * dp) * HW + tok];
            float v1 = xb[(size_t)(2 * dp + 1) * HW + tok];
            __nv_bfloat162 pr = __floats2bfloat162_rn(v0, v1);
            *reinterpret_cast<uint32_t*>(sm + SM_A + tok * RS + dp * 4) =
                *reinterpret_cast<uint32_t*>(&pr);
        }
    }

    // B prologue: tile 0 into buf 0
    {
        const char* src = reinterpret_cast<const char*>(g_cb16);
        for (int q = tid; q < NTILE * 32; q += 256) {
            int row = q >> 5, seg = q & 31;
            CP16(sb + SM_B + row * RS + seg * 16, src + row * 512 + seg * 16);
        }
        CPCOMMIT();
    }
    __syncthreads();

    float localmin[4] = {3.4e38f, 3.4e38f, 3.4e38f, 3.4e38f};
    const int rbase = wm * 32 + (lane >> 2);   // + m*16 + h*8

    for (int it = 0; it < ITERS; it++) {
        // prefetch next tile
        if (it + 1 < ITERS) {
            const char* src = reinterpret_cast<const char*>(g_cb16) + (size_t)(it + 1) * NTILE * 512;
            const uint32_t dst = sb + SM_B + ((it + 1) & 1) * (NTILE * RS);
            for (int q = tid; q < NTILE * 32; q += 256) {
                int row = q >> 5, seg = q & 31;
                CP16(dst + row * RS + seg * 16, src + row * 512 + seg * 16);
            }
            CPCOMMIT();
            CPWAIT1();
        } else {
            CPWAIT0();
        }
        __syncthreads();

        // ---- MMA: 128x64x256 this tile ----
        const uint32_t Ab = sb + SM_A + (wm * 32 + (lane & 15)) * RS + (lane >> 4) * 16;
        const uint32_t Bb = sb + SM_B + (it & 1) * (NTILE * RS)
                          + (wn * 32 + (lane & 7) + ((lane >> 4) & 1) * 8) * RS
                          + ((lane >> 3) & 1) * 16;
        float acc[2][4][4];
#pragma unroll
        for (int m = 0; m < 2; m++)
#pragma unroll
            for (int j = 0; j < 4; j++)
#pragma unroll
                for (int e = 0; e < 4; e++) acc[m][j][e] = 0.f;

#pragma unroll
        for (int k = 0; k < 16; k++) {
            uint32_t a0[4], a1[4], b0[4], b1[4];
            LDSM4(a0, Ab + k * 32);
            LDSM4(a1, Ab + 16 * RS + k * 32);
            LDSM4(b0, Bb + k * 32);
            LDSM4(b1, Bb + 16 * RS + k * 32);
            MMA16816(acc[0][0], a0, b0[0], b0[1]);
            MMA16816(acc[0][1], a0, b0[2], b0[3]);
            MMA16816(acc[0][2], a0, b1[0], b1[1]);
            MMA16816(acc[0][3], a0, b1[2], b1[3]);
            MMA16816(acc[1][0], a1, b0[0], b0[1]);
            MMA16816(acc[1][1], a1, b0[2], b0[3]);
            MMA16816(acc[1][2], a1, b1[0], b1[1]);
            MMA16816(acc[1][3], a1, b1[2], b1[3]);
        }

        // ---- pass 1: distances + running min ----
        const int c0 = it * NTILE + wn * 32 + (lane & 3) * 2;
#pragma unroll
        for (int m = 0; m < 2; m++)
#pragma unroll
            for (int j = 0; j < 4; j++)
#pragma unroll
                for (int e = 0; e < 4; e++) {
                    float dist = fmaf(-2.f, acc[m][j][e], csq_s[c0 + j * 8 + (e & 1)]);
                    acc[m][j][e] = dist;
                    int r = m * 2 + (e >> 1);
                    localmin[r] = fminf(localmin[r], dist);
                }
#pragma unroll
        for (int r = 0; r < 4; r++) {
            int row = rbase + (r >> 1) * 16 + (r & 1) * 8;
            unsigned o = ford(localmin[r]);
            if (o < minu[row]) atomicMin(&minu[row], o);
        }
        __syncthreads();

        // ---- pass 2: collect candidates ----
        float thr[4];
#pragma unroll
        for (int r = 0; r < 4; r++) {
            int row = rbase + (r >> 1) * 16 + (r & 1) * 8;
            thr[r] = ford_inv(minu[row]) + MARGIN;
        }
#pragma unroll
        for (int m = 0; m < 2; m++)
#pragma unroll
            for (int j = 0; j < 4; j++)
#pragma unroll
                for (int e = 0; e < 4; e++) {
                    int r = m * 2 + (e >> 1);
                    if (acc[m][j][e] <= thr[r]) {
                        int row  = rbase + m * 16 + (e >> 1) * 8;
                        int code = c0 + j * 8 + (e & 1);
                        int slot = atomicAdd(&cnts[row], 1);
                        if (slot < CAP) g_cand[(size_t)(n0 + row) * CAP + slot] = code;
                    }
                }
        __syncthreads();
    }

    if (tid < MTILE) g_cnt[n0 + tid] = cnts[tid];
}

// ---------------- exact rescore (one warp per token) ----------------
__global__ __launch_bounds__(256) void rescore_kernel(const float* __restrict__ x,
                                                      const float* __restrict__ cb) {
    const int n = blockIdx.x * 8 + (threadIdx.x >> 5);
    const int lane = threadIdx.x & 31;
    if (n >= NTOK) return;

    const float* xr = x + ((size_t)(n >> 10) * DIM) * HW + (n & (HW - 1));
    float xv[8];
#pragma unroll
    for (int t = 0; t < 8; t++) xv[t] = xr[(size_t)(lane + 32 * t) * HW];

    const int cnt = g_cnt[n];
    const bool full = (cnt == 0 || cnt > CAP);
    const int m = full ? KCODES : cnt;

    float best = 3.4e38f;
    int bi = KCODES;
    for (int i = 0; i < m; i++) {
        const int c = full ? i : g_cand[(size_t)n * CAP + i];
        const float* cr = cb + (size_t)c * DIM;
        float dot = 0.f;
#pragma unroll
        for (int t = 0; t < 8; t++) dot = fmaf(xv[t], cr[lane + 32 * t], dot);
#pragma unroll
        for (int o = 16; o > 0; o >>= 1) dot += __shfl_xor_sync(0xFFFFFFFFu, dot, o);
        if (lane == 0) {
            const float dist = fmaf(-2.f, dot, g_csq[c]);
            if (dist < best || (dist == best && c < bi)) { best = dist; bi = c; }
        }
    }
    if (lane == 0) g_idx[n] = bi;
}

__global__ void gather_kernel(const float* __restrict__ cb, float* __restrict__ out) {
    int o = blockIdx.x * blockDim.x + threadIdx.x;
    if (o >= NTOK * DIM) return;
    int p = o & (HW - 1);
    int d = (o >> 10) & (DIM - 1);
    int b = o >> 18;
    int n = (b << 10) + p;
    out[o] = cb[(size_t)g_idx[n] * DIM + d];
}

extern "C" void kernel_launch(void* const* d_in, const int* in_sizes, int n_in,
                              void* d_out, int out_size) {
    const float* x  = (const float*)d_in[0];
    const float* cb = (const float*)d_in[1];
    float* out = (float*)d_out;

    cudaFuncSetAttribute(sweep_kernel, cudaFuncAttributeMaxDynamicSharedMemorySize, SM_TOT);

    cvt_kernel<<<(KCODES * DIM) / 256, 256>>>(cb);
    csq_kernel<<<KCODES / 128, 128>>>(cb);
    sweep_kernel<<<NTOK / MTILE, 256, SM_TOT>>>(x);
    rescore_kernel<<<NTOK / 8, 256>>>(x, cb);
    gather_kernel<<<(NTOK * DIM) / 256, 256>>>(cb, out);
}